// round 1
// baseline (speedup 1.0000x reference)
#include <cuda_runtime.h>
#include <cuda_bf16.h>
#include <math.h>

#define N_NODE 100000
#define NE     150000
#define DK     512     // D_IN = D_OUT = 512
#define NH     8
#define CAP    64

// ---------------- scratch (device globals, allocation-free) ----------------
__device__ float g_h_o[(size_t)N_NODE * DK];   // openie projected
__device__ float g_h_e[(size_t)N_NODE * DK];   // entity projected
__device__ float g_out0[(size_t)N_NODE * DK];  // metapath 0 output
__device__ float g_out1[(size_t)N_NODE * DK];  // metapath 1 output

__device__ float g_a_e_src[(size_t)N_NODE * NH];     // att_src_e2o on h_e
__device__ float g_a_o_dst_e2o[(size_t)N_NODE * NH]; // att_dst_e2o on h_o
__device__ float g_a_o_src_o2o[(size_t)N_NODE * NH];
__device__ float g_a_o_dst_o2o[(size_t)N_NODE * NH];

__device__ int g_deg0[N_NODE];
__device__ int g_deg1[N_NODE];
__device__ int g_slots0[(size_t)N_NODE * CAP];
__device__ int g_slots1[(size_t)N_NODE * CAP];

__device__ float g_ksum[2 * DK];    // sum over nodes of tanh(out @ k_lin_w + b)
__device__ float g_outsum[2 * DK];  // column sums of out0/out1

// ---------------- init ----------------
__global__ void init_kernel() {
    int i = blockIdx.x * blockDim.x + threadIdx.x;
    if (i < N_NODE) { g_deg0[i] = 0; g_deg1[i] = 0; }
    if (i < 2 * DK) { g_ksum[i] = 0.f; g_outsum[i] = 0.f; }
}

// ---------------- GEMM: C[M,512] = A[M,512] @ B[512,512] + bias ----------------
__global__ __launch_bounds__(256)
void gemm_bias(const float* __restrict__ A, const float* __restrict__ B,
               const float* __restrict__ bias, float* __restrict__ C, int M) {
    __shared__ float As[8][128];
    __shared__ float Bs[8][128];
    int tid = threadIdx.x;
    int tx = tid & 15, ty = tid >> 4;
    int rowBase = blockIdx.y * 128;
    int colBase = blockIdx.x * 128;

    int aRow = tid >> 1;
    int aK   = (tid & 1) * 4;
    int bK   = tid >> 5;
    int bCol = (tid & 31) * 4;

    float c[8][8];
#pragma unroll
    for (int i = 0; i < 8; i++)
#pragma unroll
        for (int j = 0; j < 8; j++) c[i][j] = 0.f;

    for (int k0 = 0; k0 < DK; k0 += 8) {
        int gr = rowBase + aRow;
        float4 av = make_float4(0.f, 0.f, 0.f, 0.f);
        if (gr < M) av = *reinterpret_cast<const float4*>(A + (size_t)gr * DK + k0 + aK);
        As[aK + 0][aRow] = av.x; As[aK + 1][aRow] = av.y;
        As[aK + 2][aRow] = av.z; As[aK + 3][aRow] = av.w;
        float4 bv = *reinterpret_cast<const float4*>(B + (size_t)(k0 + bK) * DK + colBase + bCol);
        *reinterpret_cast<float4*>(&Bs[bK][bCol]) = bv;
        __syncthreads();
#pragma unroll
        for (int kk = 0; kk < 8; kk++) {
            float a[8], b[8];
#pragma unroll
            for (int i = 0; i < 8; i++) a[i] = As[kk][ty * 8 + i];
#pragma unroll
            for (int j = 0; j < 8; j++) b[j] = Bs[kk][tx * 8 + j];
#pragma unroll
            for (int i = 0; i < 8; i++)
#pragma unroll
                for (int j = 0; j < 8; j++) c[i][j] += a[i] * b[j];
        }
        __syncthreads();
    }
    float bj[8];
#pragma unroll
    for (int j = 0; j < 8; j++) bj[j] = bias[colBase + tx * 8 + j];
#pragma unroll
    for (int i = 0; i < 8; i++) {
        int gr = rowBase + ty * 8 + i;
        if (gr < M) {
            float4 v0, v1;
            v0.x = c[i][0] + bj[0]; v0.y = c[i][1] + bj[1];
            v0.z = c[i][2] + bj[2]; v0.w = c[i][3] + bj[3];
            v1.x = c[i][4] + bj[4]; v1.y = c[i][5] + bj[5];
            v1.z = c[i][6] + bj[6]; v1.w = c[i][7] + bj[7];
            float* cp = C + (size_t)gr * DK + colBase + tx * 8;
            *reinterpret_cast<float4*>(cp) = v0;
            *reinterpret_cast<float4*>(cp + 4) = v1;
        }
    }
}

// ---------------- GEMM + tanh + row-reduction (semantic k) ----------------
__global__ __launch_bounds__(256)
void gemm_tanh_reduce(const float* __restrict__ A, const float* __restrict__ B,
                      const float* __restrict__ bias, float* __restrict__ ksum_out, int M) {
    __shared__ float As[8][128];
    __shared__ float Bs[8][128];
    __shared__ float csum[128];
    int tid = threadIdx.x;
    int tx = tid & 15, ty = tid >> 4;
    int rowBase = blockIdx.y * 128;
    int colBase = blockIdx.x * 128;

    int aRow = tid >> 1;
    int aK   = (tid & 1) * 4;
    int bK   = tid >> 5;
    int bCol = (tid & 31) * 4;

    if (tid < 128) csum[tid] = 0.f;

    float c[8][8];
#pragma unroll
    for (int i = 0; i < 8; i++)
#pragma unroll
        for (int j = 0; j < 8; j++) c[i][j] = 0.f;

    for (int k0 = 0; k0 < DK; k0 += 8) {
        int gr = rowBase + aRow;
        float4 av = make_float4(0.f, 0.f, 0.f, 0.f);
        if (gr < M) av = *reinterpret_cast<const float4*>(A + (size_t)gr * DK + k0 + aK);
        As[aK + 0][aRow] = av.x; As[aK + 1][aRow] = av.y;
        As[aK + 2][aRow] = av.z; As[aK + 3][aRow] = av.w;
        float4 bv = *reinterpret_cast<const float4*>(B + (size_t)(k0 + bK) * DK + colBase + bCol);
        *reinterpret_cast<float4*>(&Bs[bK][bCol]) = bv;
        __syncthreads();
#pragma unroll
        for (int kk = 0; kk < 8; kk++) {
            float a[8], b[8];
#pragma unroll
            for (int i = 0; i < 8; i++) a[i] = As[kk][ty * 8 + i];
#pragma unroll
            for (int j = 0; j < 8; j++) b[j] = Bs[kk][tx * 8 + j];
#pragma unroll
            for (int i = 0; i < 8; i++)
#pragma unroll
                for (int j = 0; j < 8; j++) c[i][j] += a[i] * b[j];
        }
        __syncthreads();
    }
    float bj[8];
#pragma unroll
    for (int j = 0; j < 8; j++) bj[j] = bias[colBase + tx * 8 + j];
    float partial[8];
#pragma unroll
    for (int j = 0; j < 8; j++) partial[j] = 0.f;
#pragma unroll
    for (int i = 0; i < 8; i++) {
        int gr = rowBase + ty * 8 + i;
        if (gr < M) {
#pragma unroll
            for (int j = 0; j < 8; j++) partial[j] += tanhf(c[i][j] + bj[j]);
        }
    }
#pragma unroll
    for (int j = 0; j < 8; j++) atomicAdd(&csum[tx * 8 + j], partial[j]);
    __syncthreads();
    if (tid < 128) atomicAdd(&ksum_out[colBase + tid], csum[tid]);
}

// ---------------- per-node attention scalars a = <h[n,h,:], att[h,:]> ----------------
__global__ void att_kernel(const float* __restrict__ hmat,
                           const float* __restrict__ av0, const float* __restrict__ av1,
                           const float* __restrict__ av2,
                           float* __restrict__ o0, float* __restrict__ o1,
                           float* __restrict__ o2, int natt) {
    __shared__ float att_sh[3 * DK];
    for (int i = threadIdx.x; i < natt * DK; i += blockDim.x) {
        const float* src = (i < DK) ? av0 : (i < 2 * DK) ? av1 : av2;
        att_sh[i] = src[i & (DK - 1)];
    }
    __syncthreads();
    int warp = threadIdx.x >> 5, lane = threadIdx.x & 31;
    int n = blockIdx.x * 8 + warp;
    if (n >= N_NODE) return;
    float v[16];
    const float* hp = hmat + (size_t)n * DK;
#pragma unroll
    for (int r = 0; r < 16; r++) v[r] = hp[r * 32 + lane];
    for (int a = 0; a < natt; a++) {
        float p[8];
#pragma unroll
        for (int h = 0; h < 8; h++) p[h] = 0.f;
#pragma unroll
        for (int r = 0; r < 16; r++) p[r >> 1] += v[r] * att_sh[a * DK + r * 32 + lane];
#pragma unroll
        for (int off = 16; off > 0; off >>= 1)
#pragma unroll
            for (int h = 0; h < 8; h++) p[h] += __shfl_xor_sync(0xffffffffu, p[h], off);
        if (lane == 0) {
            float* op = (a == 0) ? o0 : (a == 1) ? o1 : o2;
#pragma unroll
            for (int h = 0; h < 8; h++) op[(size_t)n * NH + h] = p[h];
        }
    }
}

// ---------------- padded-CSR build ----------------
__global__ void build_csr(const int* __restrict__ dst, int* __restrict__ deg,
                          int* __restrict__ slots) {
    int e = blockIdx.x * blockDim.x + threadIdx.x;
    if (e >= NE) return;
    int dn = dst[e];
    int pos = atomicAdd(&deg[dn], 1);
    if (pos < CAP) slots[(size_t)dn * CAP + pos] = e;
}

// ---------------- GAT metapath conv: one warp per dst node ----------------
__global__ void conv_kernel(const float* __restrict__ hsrc,
                            const float* __restrict__ asrc,
                            const float* __restrict__ adst,
                            const int* __restrict__ esrc,
                            const int* __restrict__ deg,
                            const int* __restrict__ slots,
                            float* __restrict__ outp) {
    int warp = threadIdx.x >> 5, lane = threadIdx.x & 31;
    int n = blockIdx.x * 8 + warp;
    if (n >= N_NODE) return;
    int d = deg[n]; if (d > CAP) d = CAP;
    float acc[16];
#pragma unroll
    for (int r = 0; r < 16; r++) acc[r] = 0.f;

    if (d > 0) {
        float ad = (lane < 8) ? adst[(size_t)n * NH + lane] : 0.f;
        const int* sl = slots + (size_t)n * CAP;
        float mx = -1e30f;
        for (int j = 0; j < d; j++) {
            int s = esrc[sl[j]];
            if (lane < 8) {
                float al = asrc[(size_t)s * NH + lane] + ad;
                al = al > 0.f ? al : 0.2f * al;
                mx = fmaxf(mx, al);
            }
        }
        float denom = 0.f;
        for (int j = 0; j < d; j++) {
            int s = esrc[sl[j]];
            if (lane < 8) {
                float al = asrc[(size_t)s * NH + lane] + ad;
                al = al > 0.f ? al : 0.2f * al;
                denom += __expf(al - mx);
            }
        }
        denom += 1e-16f;
        int hsel = lane >> 2;  // head of this lane's 16-elem chunk
        for (int j = 0; j < d; j++) {
            int s = esrc[sl[j]];
            float w = 0.f;
            if (lane < 8) {
                float al = asrc[(size_t)s * NH + lane] + ad;
                al = al > 0.f ? al : 0.2f * al;
                w = __expf(al - mx) / denom;
            }
            float wl = __shfl_sync(0xffffffffu, w, hsel);
            const float4* hp = reinterpret_cast<const float4*>(hsrc + (size_t)s * DK + lane * 16);
#pragma unroll
            for (int q = 0; q < 4; q++) {
                float4 hv = hp[q];
                acc[q * 4 + 0] += hv.x * wl;
                acc[q * 4 + 1] += hv.y * wl;
                acc[q * 4 + 2] += hv.z * wl;
                acc[q * 4 + 3] += hv.w * wl;
            }
        }
    }
    float4* op = reinterpret_cast<float4*>(outp + (size_t)n * DK + lane * 16);
#pragma unroll
    for (int q = 0; q < 4; q++) {
        float4 o;
        o.x = fmaxf(acc[q * 4 + 0], 0.f);
        o.y = fmaxf(acc[q * 4 + 1], 0.f);
        o.z = fmaxf(acc[q * 4 + 2], 0.f);
        o.w = fmaxf(acc[q * 4 + 3], 0.f);
        op[q] = o;
    }
}

// ---------------- column sums of out_m ----------------
__global__ void colsum_kernel(const float* __restrict__ A, float* __restrict__ accum) {
    int col = threadIdx.x;           // 512 threads
    int r0 = blockIdx.x * 256;
    int r1 = r0 + 256; if (r1 > N_NODE) r1 = N_NODE;
    float s = 0.f;
    for (int r = r0; r < r1; r++) s += A[(size_t)r * DK + col];
    atomicAdd(&accum[col], s);
}

// ---------------- finalize: semantic softmax + pool + linear ----------------
__global__ void finalize_kernel(const float* __restrict__ q,
                                const float* __restrict__ lw,
                                const float* __restrict__ lb,
                                float* __restrict__ out) {
    __shared__ float red0[512], red1[512];
    __shared__ float sem0s, sem1s;
    int t = threadIdx.x;
    red0[t] = g_ksum[t] * q[t];
    red1[t] = g_ksum[DK + t] * q[t];
    __syncthreads();
    for (int s = 256; s > 0; s >>= 1) {
        if (t < s) { red0[t] += red0[t + s]; red1[t] += red1[t + s]; }
        __syncthreads();
    }
    if (t == 0) {
        float s0 = red0[0] / (float)N_NODE;
        float s1 = red1[0] / (float)N_NODE;
        float mx = fmaxf(s0, s1);
        float e0 = expf(s0 - mx), e1 = expf(s1 - mx);
        sem0s = e0 / (e0 + e1);
        sem1s = e1 / (e0 + e1);
    }
    __syncthreads();
    float pooled = (sem0s * g_outsum[t] + sem1s * g_outsum[DK + t]) / (float)N_NODE;
    red0[t] = pooled * lw[t * 2 + 0];
    red1[t] = pooled * lw[t * 2 + 1];
    __syncthreads();
    for (int s = 256; s > 0; s >>= 1) {
        if (t < s) { red0[t] += red0[t + s]; red1[t] += red1[t + s]; }
        __syncthreads();
    }
    if (t == 0) {
        out[0] = red0[0] + lb[0];
        out[1] = red1[0] + lb[1];
    }
}

// ---------------- launch ----------------
extern "C" void kernel_launch(void* const* d_in, const int* in_sizes, int n_in,
                              void* d_out, int out_size) {
    const float* x_o        = (const float*)d_in[0];
    const float* x_e        = (const float*)d_in[1];
    const int*   e_e2o      = (const int*)d_in[2];   // [2,E]: src then dst
    const int*   e_o2o      = (const int*)d_in[3];
    const float* proj_o_w   = (const float*)d_in[4];
    const float* proj_o_b   = (const float*)d_in[5];
    const float* proj_e_w   = (const float*)d_in[6];
    const float* proj_e_b   = (const float*)d_in[7];
    const float* att_src_e2o= (const float*)d_in[8];
    const float* att_dst_e2o= (const float*)d_in[9];
    const float* att_src_o2o= (const float*)d_in[10];
    const float* att_dst_o2o= (const float*)d_in[11];
    const float* k_lin_w    = (const float*)d_in[12];
    const float* k_lin_b    = (const float*)d_in[13];
    const float* q_sem      = (const float*)d_in[14];
    const float* lin_w      = (const float*)d_in[15];
    const float* lin_b      = (const float*)d_in[16];
    float* out = (float*)d_out;

    float *h_o, *h_e, *out0, *out1;
    float *a_e_src, *a_o_dst_e2o, *a_o_src_o2o, *a_o_dst_o2o;
    float *ksum, *outsum;
    int *deg0, *deg1, *slots0, *slots1;
    cudaGetSymbolAddress((void**)&h_o, g_h_o);
    cudaGetSymbolAddress((void**)&h_e, g_h_e);
    cudaGetSymbolAddress((void**)&out0, g_out0);
    cudaGetSymbolAddress((void**)&out1, g_out1);
    cudaGetSymbolAddress((void**)&a_e_src, g_a_e_src);
    cudaGetSymbolAddress((void**)&a_o_dst_e2o, g_a_o_dst_e2o);
    cudaGetSymbolAddress((void**)&a_o_src_o2o, g_a_o_src_o2o);
    cudaGetSymbolAddress((void**)&a_o_dst_o2o, g_a_o_dst_o2o);
    cudaGetSymbolAddress((void**)&ksum, g_ksum);
    cudaGetSymbolAddress((void**)&outsum, g_outsum);
    cudaGetSymbolAddress((void**)&deg0, g_deg0);
    cudaGetSymbolAddress((void**)&deg1, g_deg1);
    cudaGetSymbolAddress((void**)&slots0, g_slots0);
    cudaGetSymbolAddress((void**)&slots1, g_slots1);

    dim3 gemmGrid(DK / 128, (N_NODE + 127) / 128);

    init_kernel<<<(N_NODE + 255) / 256, 256>>>();

    gemm_bias<<<gemmGrid, 256>>>(x_o, proj_o_w, proj_o_b, h_o, N_NODE);
    gemm_bias<<<gemmGrid, 256>>>(x_e, proj_e_w, proj_e_b, h_e, N_NODE);

    att_kernel<<<(N_NODE + 7) / 8, 256>>>(h_o, att_dst_e2o, att_src_o2o, att_dst_o2o,
                                          a_o_dst_e2o, a_o_src_o2o, a_o_dst_o2o, 3);
    att_kernel<<<(N_NODE + 7) / 8, 256>>>(h_e, att_src_e2o, att_src_e2o, att_src_e2o,
                                          a_e_src, a_e_src, a_e_src, 1);

    build_csr<<<(NE + 255) / 256, 256>>>(e_e2o + NE, deg0, slots0);
    build_csr<<<(NE + 255) / 256, 256>>>(e_o2o + NE, deg1, slots1);

    conv_kernel<<<(N_NODE + 7) / 8, 256>>>(h_e, a_e_src, a_o_dst_e2o,
                                           e_e2o, deg0, slots0, out0);
    conv_kernel<<<(N_NODE + 7) / 8, 256>>>(h_o, a_o_src_o2o, a_o_dst_o2o,
                                           e_o2o, deg1, slots1, out1);

    colsum_kernel<<<(N_NODE + 255) / 256, 512>>>(out0, outsum);
    colsum_kernel<<<(N_NODE + 255) / 256, 512>>>(out1, outsum + DK);

    gemm_tanh_reduce<<<gemmGrid, 256>>>(out0, k_lin_w, k_lin_b, ksum, N_NODE);
    gemm_tanh_reduce<<<gemmGrid, 256>>>(out1, k_lin_w, k_lin_b, ksum + DK, N_NODE);

    finalize_kernel<<<1, 512>>>(q_sem, lin_w, lin_b, out);
}

// round 3
// speedup vs baseline: 2.9169x; 2.9169x over previous
#include <cuda_runtime.h>
#include <cuda_bf16.h>
#include <math.h>

#define N_NODE 100000
#define NE     150000
#define DK     512
#define NH     8
#define CAP    64

// ---------------- scratch (device globals, allocation-free) ----------------
__device__ __nv_bfloat16 g_h_o[(size_t)N_NODE * DK];
__device__ __nv_bfloat16 g_h_e[(size_t)N_NODE * DK];
__device__ __nv_bfloat16 g_out0[(size_t)N_NODE * DK];
__device__ __nv_bfloat16 g_out1[(size_t)N_NODE * DK];

__device__ float g_a_e_src[(size_t)N_NODE * NH];
__device__ float g_a_o_dst_e2o[(size_t)N_NODE * NH];
__device__ float g_a_o_src_o2o[(size_t)N_NODE * NH];
__device__ float g_a_o_dst_o2o[(size_t)N_NODE * NH];

__device__ int g_deg0[N_NODE];
__device__ int g_deg1[N_NODE];
__device__ int g_slots0[(size_t)N_NODE * CAP];
__device__ int g_slots1[(size_t)N_NODE * CAP];

__device__ float g_ksum[2 * DK];
__device__ float g_outsum[2 * DK];

__device__ __forceinline__ unsigned pack_bf16(float x, float y) {
    __nv_bfloat162 h = __floats2bfloat162_rn(x, y);
    return *reinterpret_cast<unsigned*>(&h);
}
__device__ __forceinline__ float2 unpack_bf16(unsigned u) {
    __nv_bfloat162 h = *reinterpret_cast<__nv_bfloat162*>(&u);
    return __bfloat1622float2(h);
}

// ---------------- init ----------------
__global__ void init_kernel() {
    int i = blockIdx.x * blockDim.x + threadIdx.x;
    if (i < N_NODE) { g_deg0[i] = 0; g_deg1[i] = 0; }
    if (i < 2 * DK) { g_ksum[i] = 0.f; g_outsum[i] = 0.f; }
}

// =====================================================================
// bf16 tensor-core GEMM: C[M,512] = A[M,512] @ B[512,512]
// AMODE: 0 = A is fp32 (convert on the fly), 1 = A is bf16
// EPI:   0 = bias + store bf16 C;  1 = tanh(c+bias) column-reduce to ksum
// block 256 threads, tile 128x128, K-chunk 64
// =====================================================================
template<int AMODE, int EPI>
__global__ __launch_bounds__(256)
void mma_gemm(const void* __restrict__ Ap, const float* __restrict__ B,
              const float* __restrict__ bias, void* __restrict__ Cout, int M) {
    __shared__ __align__(16) unsigned char smem[32768];   // As 16KB | Bs 16KB
    __shared__ float csum[128];
    unsigned sbase = (unsigned)__cvta_generic_to_shared(smem);
    unsigned AsB = sbase, BsB = sbase + 16384;
    uint4* smem4 = reinterpret_cast<uint4*>(smem);

    int tid = threadIdx.x;
    int lane = tid & 31, wid = tid >> 5;
    int warp_m = wid & 3, warp_n = wid >> 2;      // 4 x 2 warps; warp tile 32x64
    int rowBase = blockIdx.y * 128;
    int colBase = blockIdx.x * 128;

    if (EPI == 1 && tid < 128) csum[tid] = 0.f;

    float c[2][8][4];
#pragma unroll
    for (int i = 0; i < 2; i++)
#pragma unroll
        for (int j = 0; j < 8; j++)
#pragma unroll
            for (int q = 0; q < 4; q++) c[i][j][q] = 0.f;

    uint4 sa[4], sb[4];

    auto loadA = [&](int k0) {
#pragma unroll
        for (int i = 0; i < 4; i++) {
            int u = tid + 256 * i;
            int r = u >> 3, cch = u & 7;
            int gr = rowBase + r;
            if (AMODE == 0) {
                const float* A = (const float*)Ap;
                float4 f0 = make_float4(0.f,0.f,0.f,0.f), f1 = f0;
                if (gr < M) {
                    const float4* p = reinterpret_cast<const float4*>(A + (size_t)gr * DK + k0 + cch * 8);
                    f0 = p[0]; f1 = p[1];
                }
                sa[i] = make_uint4(pack_bf16(f0.x,f0.y), pack_bf16(f0.z,f0.w),
                                   pack_bf16(f1.x,f1.y), pack_bf16(f1.z,f1.w));
            } else {
                const __nv_bfloat16* A = (const __nv_bfloat16*)Ap;
                uint4 v = make_uint4(0,0,0,0);
                if (gr < M) v = *reinterpret_cast<const uint4*>(A + (size_t)gr * DK + k0 + cch * 8);
                sa[i] = v;
            }
        }
    };
    auto loadB = [&](int k0) {
#pragma unroll
        for (int i = 0; i < 4; i++) {
            int u = tid + 256 * i;
            int r = u >> 4, cch = u & 15;
            const float4* p = reinterpret_cast<const float4*>(B + (size_t)(k0 + r) * DK + colBase + cch * 8);
            float4 f0 = p[0], f1 = p[1];
            sb[i] = make_uint4(pack_bf16(f0.x,f0.y), pack_bf16(f0.z,f0.w),
                               pack_bf16(f1.x,f1.y), pack_bf16(f1.z,f1.w));
        }
    };
    auto storeS = [&]() {
#pragma unroll
        for (int i = 0; i < 4; i++) {
            int u = tid + 256 * i;
            { int r = u >> 3, cch = u & 7;
              smem4[r * 8 + (cch ^ (r & 7))] = sa[i]; }
            { int r = u >> 4, cch = u & 15;
              smem4[1024 + r * 16 + ((cch & 8) | ((cch & 7) ^ (r & 7)))] = sb[i]; }
        }
    };

    loadA(0); loadB(0);
    for (int k0 = 0; k0 < DK; k0 += 64) {
        storeS();
        __syncthreads();
        if (k0 + 64 < DK) { loadA(k0 + 64); loadB(k0 + 64); }
#pragma unroll
        for (int kk = 0; kk < 4; kk++) {
            unsigned a[2][4], b[8][2];
#pragma unroll
            for (int i = 0; i < 2; i++) {
                int m = lane >> 3;
                int r = warp_m * 32 + i * 16 + (m & 1) * 8 + (lane & 7);
                int cch = kk * 2 + (m >> 1);
                unsigned addr = AsB + r * 128 + ((cch ^ (r & 7)) * 16);
                asm volatile("ldmatrix.sync.aligned.m8n8.x4.shared.b16 {%0,%1,%2,%3}, [%4];"
                             : "=r"(a[i][0]), "=r"(a[i][1]), "=r"(a[i][2]), "=r"(a[i][3]) : "r"(addr));
            }
#pragma unroll
            for (int jp = 0; jp < 4; jp++) {
                int m = lane >> 3;
                int kr = kk * 16 + (m & 1) * 8 + (lane & 7);
                int cch = warp_n * 8 + jp * 2 + (m >> 1);
                unsigned addr = BsB + kr * 256 + (((cch & 8) | ((cch & 7) ^ (kr & 7))) * 16);
                asm volatile("ldmatrix.sync.aligned.m8n8.x4.trans.shared.b16 {%0,%1,%2,%3}, [%4];"
                             : "=r"(b[jp*2][0]), "=r"(b[jp*2][1]), "=r"(b[jp*2+1][0]), "=r"(b[jp*2+1][1])
                             : "r"(addr));
            }
#pragma unroll
            for (int i = 0; i < 2; i++)
#pragma unroll
                for (int j = 0; j < 8; j++) {
                    asm volatile(
                        "mma.sync.aligned.m16n8k16.row.col.f32.bf16.bf16.f32 "
                        "{%0,%1,%2,%3}, {%4,%5,%6,%7}, {%8,%9}, {%0,%1,%2,%3};"
                        : "+f"(c[i][j][0]), "+f"(c[i][j][1]), "+f"(c[i][j][2]), "+f"(c[i][j][3])
                        : "r"(a[i][0]), "r"(a[i][1]), "r"(a[i][2]), "r"(a[i][3]),
                          "r"(b[j][0]), "r"(b[j][1]));
                }
        }
        __syncthreads();
    }

    int g = lane >> 2, t = lane & 3;
    if (EPI == 0) {
        __nv_bfloat16* C = (__nv_bfloat16*)Cout;
#pragma unroll
        for (int j = 0; j < 8; j++) {
            int col = colBase + warp_n * 64 + j * 8 + 2 * t;
            float b0 = bias[col], b1 = bias[col + 1];
#pragma unroll
            for (int i = 0; i < 2; i++) {
                int r0 = rowBase + warp_m * 32 + i * 16 + g;
                if (r0 < M)
                    *reinterpret_cast<unsigned*>(C + (size_t)r0 * DK + col) =
                        pack_bf16(c[i][j][0] + b0, c[i][j][1] + b1);
                if (r0 + 8 < M)
                    *reinterpret_cast<unsigned*>(C + (size_t)(r0 + 8) * DK + col) =
                        pack_bf16(c[i][j][2] + b0, c[i][j][3] + b1);
            }
        }
    } else {
        float* ksum = (float*)Cout;
#pragma unroll
        for (int j = 0; j < 8; j++) {
            int col = colBase + warp_n * 64 + j * 8 + 2 * t;
            float b0 = bias[col], b1 = bias[col + 1];
            float s0 = 0.f, s1 = 0.f;
#pragma unroll
            for (int i = 0; i < 2; i++) {
                int r0 = rowBase + warp_m * 32 + i * 16 + g;
                if (r0 < M)     { s0 += tanhf(c[i][j][0] + b0); s1 += tanhf(c[i][j][1] + b1); }
                if (r0 + 8 < M) { s0 += tanhf(c[i][j][2] + b0); s1 += tanhf(c[i][j][3] + b1); }
            }
            atomicAdd(&csum[warp_n * 64 + j * 8 + 2 * t], s0);
            atomicAdd(&csum[warp_n * 64 + j * 8 + 2 * t + 1], s1);
        }
        __syncthreads();
        if (tid < 128) atomicAdd(&ksum[colBase + tid], csum[tid]);
    }
}

// ---------------- per-node attention scalars (h is bf16) ----------------
__global__ void att_kernel(const __nv_bfloat16* __restrict__ hmat,
                           const float* __restrict__ av0, const float* __restrict__ av1,
                           const float* __restrict__ av2,
                           float* __restrict__ o0, float* __restrict__ o1,
                           float* __restrict__ o2, int natt) {
    __shared__ float att_sh[3 * DK];
    for (int i = threadIdx.x; i < natt * DK; i += blockDim.x) {
        const float* src = (i < DK) ? av0 : (i < 2 * DK) ? av1 : av2;
        att_sh[i] = src[i & (DK - 1)];
    }
    __syncthreads();
    int warp = threadIdx.x >> 5, lane = threadIdx.x & 31;
    int n = blockIdx.x * 8 + warp;
    if (n >= N_NODE) return;
    const unsigned* hp = reinterpret_cast<const unsigned*>(hmat + (size_t)n * DK);
    unsigned vp[8];
#pragma unroll
    for (int r = 0; r < 8; r++) vp[r] = hp[r * 32 + lane];   // pair idx r*32+lane, head=r
    for (int a = 0; a < natt; a++) {
        float p[8];
#pragma unroll
        for (int h = 0; h < 8; h++) {
            float2 v = unpack_bf16(vp[h]);
            const float* ap = att_sh + a * DK + h * 64 + lane * 2;
            p[h] = v.x * ap[0] + v.y * ap[1];
        }
#pragma unroll
        for (int off = 16; off > 0; off >>= 1)
#pragma unroll
            for (int h = 0; h < 8; h++) p[h] += __shfl_xor_sync(0xffffffffu, p[h], off);
        if (lane == 0) {
            float* op = (a == 0) ? o0 : (a == 1) ? o1 : o2;
#pragma unroll
            for (int h = 0; h < 8; h++) op[(size_t)n * NH + h] = p[h];
        }
    }
}

// ---------------- padded-CSR build ----------------
__global__ void build_csr(const int* __restrict__ dst, int* __restrict__ deg,
                          int* __restrict__ slots) {
    int e = blockIdx.x * blockDim.x + threadIdx.x;
    if (e >= NE) return;
    int dn = dst[e];
    int pos = atomicAdd(&deg[dn], 1);
    if (pos < CAP) slots[(size_t)dn * CAP + pos] = e;
}

// ---------------- GAT conv: one warp per dst node, bf16 gather, fused colsum ----------------
__global__ void conv_kernel(const __nv_bfloat16* __restrict__ hsrc,
                            const float* __restrict__ asrc,
                            const float* __restrict__ adst,
                            const int* __restrict__ esrc,
                            const int* __restrict__ deg,
                            const int* __restrict__ slots,
                            __nv_bfloat16* __restrict__ outp,
                            float* __restrict__ outsum) {
    __shared__ float bsum[512];
    for (int i = threadIdx.x; i < 512; i += 256) bsum[i] = 0.f;
    __syncthreads();
    int warp = threadIdx.x >> 5, lane = threadIdx.x & 31;
    int n = blockIdx.x * 8 + warp;
    float acc[16];
#pragma unroll
    for (int r = 0; r < 16; r++) acc[r] = 0.f;

    if (n < N_NODE) {
        int d = deg[n]; if (d > CAP) d = CAP;
        if (d > 0) {
            float ad = (lane < 8) ? adst[(size_t)n * NH + lane] : 0.f;
            const int* sl = slots + (size_t)n * CAP;
            float mx = -1e30f;
            for (int j = 0; j < d; j++) {
                int s = esrc[sl[j]];
                if (lane < 8) {
                    float al = asrc[(size_t)s * NH + lane] + ad;
                    al = al > 0.f ? al : 0.2f * al;
                    mx = fmaxf(mx, al);
                }
            }
            float denom = 0.f;
            for (int j = 0; j < d; j++) {
                int s = esrc[sl[j]];
                if (lane < 8) {
                    float al = asrc[(size_t)s * NH + lane] + ad;
                    al = al > 0.f ? al : 0.2f * al;
                    denom += __expf(al - mx);
                }
            }
            denom += 1e-16f;
            int h1 = lane >> 3, h2 = 4 + (lane >> 3);
            for (int j = 0; j < d; j++) {
                int s = esrc[sl[j]];
                float w = 0.f;
                if (lane < 8) {
                    float al = asrc[(size_t)s * NH + lane] + ad;
                    al = al > 0.f ? al : 0.2f * al;
                    w = __expf(al - mx) / denom;
                }
                float w1 = __shfl_sync(0xffffffffu, w, h1);
                float w2 = __shfl_sync(0xffffffffu, w, h2);
                const uint4* hp = reinterpret_cast<const uint4*>(hsrc + (size_t)s * DK);
                uint4 v1 = hp[lane];       // elems [8*lane, 8*lane+8)
                uint4 v2 = hp[lane + 32];  // elems [256+8*lane, +8)
                const unsigned* u1 = &v1.x;
                const unsigned* u2 = &v2.x;
#pragma unroll
                for (int q = 0; q < 4; q++) {
                    float2 f1 = unpack_bf16(u1[q]);
                    float2 f2 = unpack_bf16(u2[q]);
                    acc[q * 2 + 0] += f1.x * w1; acc[q * 2 + 1] += f1.y * w1;
                    acc[8 + q * 2 + 0] += f2.x * w2; acc[8 + q * 2 + 1] += f2.y * w2;
                }
            }
        }
        uint4 o1, o2;
        unsigned* p1 = &o1.x; unsigned* p2 = &o2.x;
#pragma unroll
        for (int q = 0; q < 4; q++) {
            float a0 = fmaxf(acc[q*2+0], 0.f),  a1 = fmaxf(acc[q*2+1], 0.f);
            float b0 = fmaxf(acc[8+q*2+0], 0.f), b1 = fmaxf(acc[8+q*2+1], 0.f);
            p1[q] = pack_bf16(a0, a1);
            p2[q] = pack_bf16(b0, b1);
            atomicAdd(&bsum[lane * 8 + q * 2 + 0], a0);
            atomicAdd(&bsum[lane * 8 + q * 2 + 1], a1);
            atomicAdd(&bsum[256 + lane * 8 + q * 2 + 0], b0);
            atomicAdd(&bsum[256 + lane * 8 + q * 2 + 1], b1);
        }
        uint4* op = reinterpret_cast<uint4*>(outp + (size_t)n * DK);
        op[lane] = o1; op[lane + 32] = o2;
    }
    __syncthreads();
    for (int i = threadIdx.x; i < 512; i += 256) atomicAdd(&outsum[i], bsum[i]);
}

// ---------------- finalize ----------------
__global__ void finalize_kernel(const float* __restrict__ q,
                                const float* __restrict__ lw,
                                const float* __restrict__ lb,
                                float* __restrict__ out) {
    __shared__ float red0[512], red1[512];
    __shared__ float sem0s, sem1s;
    int t = threadIdx.x;
    red0[t] = g_ksum[t] * q[t];
    red1[t] = g_ksum[DK + t] * q[t];
    __syncthreads();
    for (int s = 256; s > 0; s >>= 1) {
        if (t < s) { red0[t] += red0[t + s]; red1[t] += red1[t + s]; }
        __syncthreads();
    }
    if (t == 0) {
        float s0 = red0[0] / (float)N_NODE;
        float s1 = red1[0] / (float)N_NODE;
        float mx = fmaxf(s0, s1);
        float e0 = expf(s0 - mx), e1 = expf(s1 - mx);
        sem0s = e0 / (e0 + e1);
        sem1s = e1 / (e0 + e1);
    }
    __syncthreads();
    float pooled = (sem0s * g_outsum[t] + sem1s * g_outsum[DK + t]) / (float)N_NODE;
    red0[t] = pooled * lw[t * 2 + 0];
    red1[t] = pooled * lw[t * 2 + 1];
    __syncthreads();
    for (int s = 256; s > 0; s >>= 1) {
        if (t < s) { red0[t] += red0[t + s]; red1[t] += red1[t + s]; }
        __syncthreads();
    }
    if (t == 0) {
        out[0] = red0[0] + lb[0];
        out[1] = red1[0] + lb[1];
    }
}

// ---------------- launch ----------------
extern "C" void kernel_launch(void* const* d_in, const int* in_sizes, int n_in,
                              void* d_out, int out_size) {
    const float* x_o        = (const float*)d_in[0];
    const float* x_e        = (const float*)d_in[1];
    const int*   e_e2o      = (const int*)d_in[2];
    const int*   e_o2o      = (const int*)d_in[3];
    const float* proj_o_w   = (const float*)d_in[4];
    const float* proj_o_b   = (const float*)d_in[5];
    const float* proj_e_w   = (const float*)d_in[6];
    const float* proj_e_b   = (const float*)d_in[7];
    const float* att_src_e2o= (const float*)d_in[8];
    const float* att_dst_e2o= (const float*)d_in[9];
    const float* att_src_o2o= (const float*)d_in[10];
    const float* att_dst_o2o= (const float*)d_in[11];
    const float* k_lin_w    = (const float*)d_in[12];
    const float* k_lin_b    = (const float*)d_in[13];
    const float* q_sem      = (const float*)d_in[14];
    const float* lin_w      = (const float*)d_in[15];
    const float* lin_b      = (const float*)d_in[16];
    float* out = (float*)d_out;

    __nv_bfloat16 *h_o, *h_e, *out0, *out1;
    float *a_e_src, *a_o_dst_e2o, *a_o_src_o2o, *a_o_dst_o2o, *ksum, *outsum;
    int *deg0, *deg1, *slots0, *slots1;
    cudaGetSymbolAddress((void**)&h_o, g_h_o);
    cudaGetSymbolAddress((void**)&h_e, g_h_e);
    cudaGetSymbolAddress((void**)&out0, g_out0);
    cudaGetSymbolAddress((void**)&out1, g_out1);
    cudaGetSymbolAddress((void**)&a_e_src, g_a_e_src);
    cudaGetSymbolAddress((void**)&a_o_dst_e2o, g_a_o_dst_e2o);
    cudaGetSymbolAddress((void**)&a_o_src_o2o, g_a_o_src_o2o);
    cudaGetSymbolAddress((void**)&a_o_dst_o2o, g_a_o_dst_o2o);
    cudaGetSymbolAddress((void**)&ksum, g_ksum);
    cudaGetSymbolAddress((void**)&outsum, g_outsum);
    cudaGetSymbolAddress((void**)&deg0, g_deg0);
    cudaGetSymbolAddress((void**)&deg1, g_deg1);
    cudaGetSymbolAddress((void**)&slots0, g_slots0);
    cudaGetSymbolAddress((void**)&slots1, g_slots1);

    dim3 gemmGrid(DK / 128, (N_NODE + 127) / 128);

    init_kernel<<<(N_NODE + 255) / 256, 256>>>();

    mma_gemm<0,0><<<gemmGrid, 256>>>(x_o, proj_o_w, proj_o_b, h_o, N_NODE);
    mma_gemm<0,0><<<gemmGrid, 256>>>(x_e, proj_e_w, proj_e_b, h_e, N_NODE);

    att_kernel<<<(N_NODE + 7) / 8, 256>>>(h_o, att_dst_e2o, att_src_o2o, att_dst_o2o,
                                          a_o_dst_e2o, a_o_src_o2o, a_o_dst_o2o, 3);
    att_kernel<<<(N_NODE + 7) / 8, 256>>>(h_e, att_src_e2o, att_src_e2o, att_src_e2o,
                                          a_e_src, a_e_src, a_e_src, 1);

    build_csr<<<(NE + 255) / 256, 256>>>(e_e2o + NE, deg0, slots0);
    build_csr<<<(NE + 255) / 256, 256>>>(e_o2o + NE, deg1, slots1);

    conv_kernel<<<(N_NODE + 7) / 8, 256>>>(h_e, a_e_src, a_o_dst_e2o,
                                           e_e2o, deg0, slots0, out0, outsum);
    conv_kernel<<<(N_NODE + 7) / 8, 256>>>(h_o, a_o_src_o2o, a_o_dst_o2o,
                                           e_o2o, deg1, slots1, out1, outsum + DK);

    mma_gemm<1,1><<<gemmGrid, 256>>>(out0, k_lin_w, k_lin_b, ksum, N_NODE);
    mma_gemm<1,1><<<gemmGrid, 256>>>(out1, k_lin_w, k_lin_b, ksum + DK, N_NODE);

    finalize_kernel<<<1, 512>>>(q_sem, lin_w, lin_b, out);
}

// round 7
// speedup vs baseline: 4.6847x; 1.6060x over previous
#include <cuda_runtime.h>
#include <cuda_bf16.h>
#include <math.h>

#define N_NODE 100000
#define NE     150000
#define DK     512
#define NH     8
#define CAP    64

// ---------------- scratch (device globals, allocation-free) ----------------
__device__ __nv_bfloat16 g_h_o[(size_t)N_NODE * DK];
__device__ __nv_bfloat16 g_h_e[(size_t)N_NODE * DK];
__device__ __nv_bfloat16 g_out0[(size_t)N_NODE * DK];
__device__ __nv_bfloat16 g_out1[(size_t)N_NODE * DK];

__device__ __nv_bfloat16 g_bw_o[DK * DK];   // bf16 copies of weights, same [k, n] layout
__device__ __nv_bfloat16 g_bw_e[DK * DK];
__device__ __nv_bfloat16 g_bw_k[DK * DK];

__device__ float g_a_e_src[(size_t)N_NODE * NH];
__device__ float g_a_o_dst_e2o[(size_t)N_NODE * NH];
__device__ float g_a_o_src_o2o[(size_t)N_NODE * NH];
__device__ float g_a_o_dst_o2o[(size_t)N_NODE * NH];

__device__ int g_deg0[N_NODE];
__device__ int g_deg1[N_NODE];
__device__ int g_slots0[(size_t)N_NODE * CAP];
__device__ int g_slots1[(size_t)N_NODE * CAP];

__device__ float g_kdot[2];
__device__ float g_outsum[2 * DK];

__device__ __forceinline__ unsigned pack_bf16(float x, float y) {
    __nv_bfloat162 h = __floats2bfloat162_rn(x, y);
    return *reinterpret_cast<unsigned*>(&h);
}
__device__ __forceinline__ float2 unpack_bf16(unsigned u) {
    __nv_bfloat162 h = *reinterpret_cast<__nv_bfloat162*>(&u);
    return __bfloat1622float2(h);
}

// ---------------- init ----------------
__global__ void init_kernel() {
    int i = blockIdx.x * blockDim.x + threadIdx.x;
    if (i < N_NODE) { g_deg0[i] = 0; g_deg1[i] = 0; }
    if (i < 2 * DK) g_outsum[i] = 0.f;
    if (i < 2) g_kdot[i] = 0.f;
}

// ---------------- fp32 -> bf16 weight convert ----------------
__global__ void convert_w(const float* __restrict__ W, __nv_bfloat16* __restrict__ O) {
    int i = blockIdx.x * blockDim.x + threadIdx.x;      // over pairs
    if (i < DK * DK / 2) {
        float2 f = reinterpret_cast<const float2*>(W)[i];
        reinterpret_cast<unsigned*>(O)[i] = pack_bf16(f.x, f.y);
    }
}

// =====================================================================
// bf16 mma.sync GEMM: C[M,512] = A[M,512] @ B[512,512] (B pre-converted bf16)
// AMODE: 0 = A fp32 (convert on the fly), 1 = A bf16
// EPI 0: bias + store bf16 C + NATT fused per-head attention dots
// EPI 1: sum_n sum_f tanh(c+bias)*q[f] -> one atomicAdd(kdot) per block
// block 256 threads, tile 128x128, K-chunk 64, grid (4, ceil(M/128))
// =====================================================================
template<int AMODE, int EPI, int NATT>
__global__ __launch_bounds__(256)
void mma_gemm(const void* __restrict__ Ap, const __nv_bfloat16* __restrict__ B,
              const float* __restrict__ bias, __nv_bfloat16* __restrict__ Cout,
              const float* __restrict__ av0, const float* __restrict__ av1,
              const float* __restrict__ av2,
              float* __restrict__ aout0, float* __restrict__ aout1,
              float* __restrict__ aout2,
              const float* __restrict__ qsem, float* __restrict__ kdot, int M) {
    __shared__ __align__(16) unsigned char smem[32768];   // As 16KB | Bs 16KB
    __shared__ float bias_sh[DK];
    __shared__ float aux_sh[(NATT > 0 || EPI == 1) ? (EPI == 1 ? DK : NATT * DK) : 1];
    __shared__ float wred[8];
    unsigned sbase = (unsigned)__cvta_generic_to_shared(smem);
    unsigned AsB = sbase, BsB = sbase + 16384;
    uint4* smem4 = reinterpret_cast<uint4*>(smem);

    int tid = threadIdx.x;
    int lane = tid & 31, wid = tid >> 5;
    int warp_m = wid & 3, warp_n = wid >> 2;      // 4 x 2 warps; warp tile 32x64
    int rowBase = blockIdx.y * 128;
    int colBase = blockIdx.x * 128;

    for (int i = tid; i < DK; i += 256) {
        bias_sh[i] = bias[i];
        if (EPI == 1) aux_sh[i] = qsem[i];
    }
    if (EPI == 0 && NATT > 0) {
        for (int i = tid; i < NATT * DK; i += 256) {
            const float* src = (i < DK) ? av0 : (i < 2 * DK) ? av1 : av2;
            aux_sh[i] = src[i & (DK - 1)];
        }
    }
    __syncthreads();

    float c[2][8][4];
#pragma unroll
    for (int i = 0; i < 2; i++)
#pragma unroll
        for (int j = 0; j < 8; j++)
#pragma unroll
            for (int q = 0; q < 4; q++) c[i][j][q] = 0.f;

    uint4 sa[4], sb[4];

    auto loadA = [&](int k0) {
#pragma unroll
        for (int i = 0; i < 4; i++) {
            int u = tid + 256 * i;
            int r = u >> 3, cch = u & 7;
            int gr = rowBase + r;
            if (AMODE == 0) {
                const float* A = (const float*)Ap;
                float4 f0 = make_float4(0.f,0.f,0.f,0.f), f1 = f0;
                if (gr < M) {
                    const float4* p = reinterpret_cast<const float4*>(A + (size_t)gr * DK + k0 + cch * 8);
                    f0 = p[0]; f1 = p[1];
                }
                sa[i] = make_uint4(pack_bf16(f0.x,f0.y), pack_bf16(f0.z,f0.w),
                                   pack_bf16(f1.x,f1.y), pack_bf16(f1.z,f1.w));
            } else {
                const __nv_bfloat16* A = (const __nv_bfloat16*)Ap;
                uint4 v = make_uint4(0,0,0,0);
                if (gr < M) v = *reinterpret_cast<const uint4*>(A + (size_t)gr * DK + k0 + cch * 8);
                sa[i] = v;
            }
        }
    };
    auto loadB = [&](int k0) {
#pragma unroll
        for (int i = 0; i < 4; i++) {
            int u = tid + 256 * i;
            int r = u >> 4, cch = u & 15;
            sb[i] = *reinterpret_cast<const uint4*>(B + (size_t)(k0 + r) * DK + colBase + cch * 8);
        }
    };
    auto storeS = [&]() {
#pragma unroll
        for (int i = 0; i < 4; i++) {
            int u = tid + 256 * i;
            { int r = u >> 3, cch = u & 7;
              smem4[r * 8 + (cch ^ (r & 7))] = sa[i]; }
            { int r = u >> 4, cch = u & 15;
              smem4[1024 + r * 16 + ((cch & 8) | ((cch & 7) ^ (r & 7)))] = sb[i]; }
        }
    };

    loadA(0); loadB(0);
    for (int k0 = 0; k0 < DK; k0 += 64) {
        storeS();
        __syncthreads();
        if (k0 + 64 < DK) { loadA(k0 + 64); loadB(k0 + 64); }
#pragma unroll
        for (int kk = 0; kk < 4; kk++) {
            unsigned a[2][4], b[8][2];
#pragma unroll
            for (int i = 0; i < 2; i++) {
                int m = lane >> 3;
                int r = warp_m * 32 + i * 16 + (m & 1) * 8 + (lane & 7);
                int cch = kk * 2 + (m >> 1);
                unsigned addr = AsB + r * 128 + ((cch ^ (r & 7)) * 16);
                asm volatile("ldmatrix.sync.aligned.m8n8.x4.shared.b16 {%0,%1,%2,%3}, [%4];"
                             : "=r"(a[i][0]), "=r"(a[i][1]), "=r"(a[i][2]), "=r"(a[i][3]) : "r"(addr));
            }
#pragma unroll
            for (int jp = 0; jp < 4; jp++) {
                int m = lane >> 3;
                int kr = kk * 16 + (m & 1) * 8 + (lane & 7);
                int cch = warp_n * 8 + jp * 2 + (m >> 1);
                unsigned addr = BsB + kr * 256 + (((cch & 8) | ((cch & 7) ^ (kr & 7))) * 16);
                asm volatile("ldmatrix.sync.aligned.m8n8.x4.trans.shared.b16 {%0,%1,%2,%3}, [%4];"
                             : "=r"(b[jp*2][0]), "=r"(b[jp*2][1]), "=r"(b[jp*2+1][0]), "=r"(b[jp*2+1][1])
                             : "r"(addr));
            }
#pragma unroll
            for (int i = 0; i < 2; i++)
#pragma unroll
                for (int j = 0; j < 8; j++) {
                    asm volatile(
                        "mma.sync.aligned.m16n8k16.row.col.f32.bf16.bf16.f32 "
                        "{%0,%1,%2,%3}, {%4,%5,%6,%7}, {%8,%9}, {%0,%1,%2,%3};"
                        : "+f"(c[i][j][0]), "+f"(c[i][j][1]), "+f"(c[i][j][2]), "+f"(c[i][j][3])
                        : "r"(a[i][0]), "r"(a[i][1]), "r"(a[i][2]), "r"(a[i][3]),
                          "r"(b[j][0]), "r"(b[j][1]));
                }
        }
        __syncthreads();
    }

    // ---------------- epilogue ----------------
    int g = lane >> 2, t = lane & 3;
    if (EPI == 0) {
        __nv_bfloat16* C = Cout;
        float aacc[(NATT > 0 ? NATT : 1)][4];
#pragma unroll
        for (int v = 0; v < (NATT > 0 ? NATT : 1); v++)
#pragma unroll
            for (int f = 0; f < 4; f++) aacc[v][f] = 0.f;

#pragma unroll
        for (int j = 0; j < 8; j++) {
            int col = colBase + warp_n * 64 + j * 8 + 2 * t;
            float b0 = bias_sh[col], b1 = bias_sh[col + 1];
#pragma unroll
            for (int i = 0; i < 2; i++) {
                int r0 = rowBase + warp_m * 32 + i * 16 + g;
                float v0 = c[i][j][0] + b0, v1 = c[i][j][1] + b1;
                float v2 = c[i][j][2] + b0, v3 = c[i][j][3] + b1;
                if (r0 < M)
                    *reinterpret_cast<unsigned*>(C + (size_t)r0 * DK + col) = pack_bf16(v0, v1);
                if (r0 + 8 < M)
                    *reinterpret_cast<unsigned*>(C + (size_t)(r0 + 8) * DK + col) = pack_bf16(v2, v3);
#pragma unroll
                for (int v = 0; v < NATT; v++) {
                    float a0 = aux_sh[v * DK + col], a1 = aux_sh[v * DK + col + 1];
                    aacc[v][i * 2 + 0] += v0 * a0 + v1 * a1;
                    aacc[v][i * 2 + 1] += v2 * a0 + v3 * a1;
                }
            }
        }
        if (NATT > 0) {
            // reduce over the 4 't' lanes (each (bx, warp_n) owns one head's 64 cols)
#pragma unroll
            for (int v = 0; v < NATT; v++)
#pragma unroll
                for (int f = 0; f < 4; f++) {
                    aacc[v][f] += __shfl_xor_sync(0xffffffffu, aacc[v][f], 1);
                    aacc[v][f] += __shfl_xor_sync(0xffffffffu, aacc[v][f], 2);
                }
            if (t == 0) {
                int ghead = blockIdx.x * 2 + warp_n;
#pragma unroll
                for (int f = 0; f < 4; f++) {
                    int row = rowBase + warp_m * 32 + (f & 1) * 8 + (f >> 1) * 16 + g;
                    if (row < M) {
#pragma unroll
                        for (int v = 0; v < NATT; v++) {
                            float* ao = (v == 0) ? aout0 : (v == 1) ? aout1 : aout2;
                            ao[(size_t)row * NH + ghead] = aacc[v][f];
                        }
                    }
                }
            }
        }
    } else {
        float sq = 0.f;
#pragma unroll
        for (int j = 0; j < 8; j++) {
            int col = colBase + warp_n * 64 + j * 8 + 2 * t;
            float b0 = bias_sh[col], b1 = bias_sh[col + 1];
            float q0 = aux_sh[col], q1 = aux_sh[col + 1];
#pragma unroll
            for (int i = 0; i < 2; i++) {
                int r0 = rowBase + warp_m * 32 + i * 16 + g;
                if (r0 < M)
                    sq += tanhf(c[i][j][0] + b0) * q0 + tanhf(c[i][j][1] + b1) * q1;
                if (r0 + 8 < M)
                    sq += tanhf(c[i][j][2] + b0) * q0 + tanhf(c[i][j][3] + b1) * q1;
            }
        }
#pragma unroll
        for (int off = 16; off > 0; off >>= 1)
            sq += __shfl_xor_sync(0xffffffffu, sq, off);
        if (lane == 0) wred[wid] = sq;
        __syncthreads();
        if (tid == 0) {
            float s = 0.f;
#pragma unroll
            for (int w = 0; w < 8; w++) s += wred[w];
            atomicAdd(kdot, s);
        }
    }
}

// ---------------- padded-CSR build ----------------
__global__ void build_csr(const int* __restrict__ dst, int* __restrict__ deg,
                          int* __restrict__ slots) {
    int e = blockIdx.x * blockDim.x + threadIdx.x;
    if (e >= NE) return;
    int dn = dst[e];
    int pos = atomicAdd(&deg[dn], 1);
    if (pos < CAP) slots[(size_t)dn * CAP + pos] = e;
}

// ---------------- GAT conv: one warp per dst node, bf16 gather, fused colsum ----------------
__global__ void conv_kernel(const __nv_bfloat16* __restrict__ hsrc,
                            const float* __restrict__ asrc,
                            const float* __restrict__ adst,
                            const int* __restrict__ esrc,
                            const int* __restrict__ deg,
                            const int* __restrict__ slots,
                            __nv_bfloat16* __restrict__ outp,
                            float* __restrict__ outsum) {
    __shared__ float bsum[512];
    for (int i = threadIdx.x; i < 512; i += 256) bsum[i] = 0.f;
    __syncthreads();
    int warp = threadIdx.x >> 5, lane = threadIdx.x & 31;
    int n = blockIdx.x * 8 + warp;
    float acc[16];
#pragma unroll
    for (int r = 0; r < 16; r++) acc[r] = 0.f;

    if (n < N_NODE) {
        int d = deg[n]; if (d > CAP) d = CAP;
        if (d > 0) {
            float ad = (lane < 8) ? adst[(size_t)n * NH + lane] : 0.f;
            const int* sl = slots + (size_t)n * CAP;
            float mx = -1e30f;
            for (int j = 0; j < d; j++) {
                int s = esrc[sl[j]];
                if (lane < 8) {
                    float al = asrc[(size_t)s * NH + lane] + ad;
                    al = al > 0.f ? al : 0.2f * al;
                    mx = fmaxf(mx, al);
                }
            }
            float denom = 0.f;
            for (int j = 0; j < d; j++) {
                int s = esrc[sl[j]];
                if (lane < 8) {
                    float al = asrc[(size_t)s * NH + lane] + ad;
                    al = al > 0.f ? al : 0.2f * al;
                    denom += __expf(al - mx);
                }
            }
            denom += 1e-16f;
            int h1 = lane >> 3, h2 = 4 + (lane >> 3);
            for (int j = 0; j < d; j++) {
                int s = esrc[sl[j]];
                float w = 0.f;
                if (lane < 8) {
                    float al = asrc[(size_t)s * NH + lane] + ad;
                    al = al > 0.f ? al : 0.2f * al;
                    w = __expf(al - mx) / denom;
                }
                float w1 = __shfl_sync(0xffffffffu, w, h1);
                float w2 = __shfl_sync(0xffffffffu, w, h2);
                const uint4* hp = reinterpret_cast<const uint4*>(hsrc + (size_t)s * DK);
                uint4 v1 = hp[lane];
                uint4 v2 = hp[lane + 32];
                const unsigned* u1 = &v1.x;
                const unsigned* u2 = &v2.x;
#pragma unroll
                for (int q = 0; q < 4; q++) {
                    float2 f1 = unpack_bf16(u1[q]);
                    float2 f2 = unpack_bf16(u2[q]);
                    acc[q * 2 + 0] += f1.x * w1; acc[q * 2 + 1] += f1.y * w1;
                    acc[8 + q * 2 + 0] += f2.x * w2; acc[8 + q * 2 + 1] += f2.y * w2;
                }
            }
        }
        uint4 o1, o2;
        unsigned* p1 = &o1.x; unsigned* p2 = &o2.x;
#pragma unroll
        for (int q = 0; q < 4; q++) {
            float a0 = fmaxf(acc[q*2+0], 0.f),  a1 = fmaxf(acc[q*2+1], 0.f);
            float b0 = fmaxf(acc[8+q*2+0], 0.f), b1 = fmaxf(acc[8+q*2+1], 0.f);
            p1[q] = pack_bf16(a0, a1);
            p2[q] = pack_bf16(b0, b1);
            atomicAdd(&bsum[lane * 8 + q * 2 + 0], a0);
            atomicAdd(&bsum[lane * 8 + q * 2 + 1], a1);
            atomicAdd(&bsum[256 + lane * 8 + q * 2 + 0], b0);
            atomicAdd(&bsum[256 + lane * 8 + q * 2 + 1], b1);
        }
        uint4* op = reinterpret_cast<uint4*>(outp + (size_t)n * DK);
        op[lane] = o1; op[lane + 32] = o2;
    }
    __syncthreads();
    for (int i = threadIdx.x; i < 512; i += 256) atomicAdd(&outsum[i], bsum[i]);
}

// ---------------- finalize ----------------
__global__ void finalize_kernel(const float* __restrict__ lw,
                                const float* __restrict__ lb,
                                float* __restrict__ out) {
    __shared__ float red0[512], red1[512];
    __shared__ float sem0s, sem1s;
    int t = threadIdx.x;
    if (t == 0) {
        float s0 = g_kdot[0] / (float)N_NODE;
        float s1 = g_kdot[1] / (float)N_NODE;
        float mx = fmaxf(s0, s1);
        float e0 = expf(s0 - mx), e1 = expf(s1 - mx);
        sem0s = e0 / (e0 + e1);
        sem1s = e1 / (e0 + e1);
    }
    __syncthreads();
    float pooled = (sem0s * g_outsum[t] + sem1s * g_outsum[DK + t]) / (float)N_NODE;
    red0[t] = pooled * lw[t * 2 + 0];
    red1[t] = pooled * lw[t * 2 + 1];
    __syncthreads();
    for (int s = 256; s > 0; s >>= 1) {
        if (t < s) { red0[t] += red0[t + s]; red1[t] += red1[t + s]; }
        __syncthreads();
    }
    if (t == 0) {
        out[0] = red0[0] + lb[0];
        out[1] = red1[0] + lb[1];
    }
}

// ---------------- launch ----------------
extern "C" void kernel_launch(void* const* d_in, const int* in_sizes, int n_in,
                              void* d_out, int out_size) {
    const float* x_o        = (const float*)d_in[0];
    const float* x_e        = (const float*)d_in[1];
    const int*   e_e2o      = (const int*)d_in[2];
    const int*   e_o2o      = (const int*)d_in[3];
    const float* proj_o_w   = (const float*)d_in[4];
    const float* proj_o_b   = (const float*)d_in[5];
    const float* proj_e_w   = (const float*)d_in[6];
    const float* proj_e_b   = (const float*)d_in[7];
    const float* att_src_e2o= (const float*)d_in[8];
    const float* att_dst_e2o= (const float*)d_in[9];
    const float* att_src_o2o= (const float*)d_in[10];
    const float* att_dst_o2o= (const float*)d_in[11];
    const float* k_lin_w    = (const float*)d_in[12];
    const float* k_lin_b    = (const float*)d_in[13];
    const float* q_sem      = (const float*)d_in[14];
    const float* lin_w      = (const float*)d_in[15];
    const float* lin_b      = (const float*)d_in[16];
    float* out = (float*)d_out;

    __nv_bfloat16 *h_o, *h_e, *out0, *out1, *bw_o, *bw_e, *bw_k;
    float *a_e_src, *a_o_dst_e2o, *a_o_src_o2o, *a_o_dst_o2o, *kdot, *outsum;
    int *deg0, *deg1, *slots0, *slots1;
    cudaGetSymbolAddress((void**)&h_o, g_h_o);
    cudaGetSymbolAddress((void**)&h_e, g_h_e);
    cudaGetSymbolAddress((void**)&out0, g_out0);
    cudaGetSymbolAddress((void**)&out1, g_out1);
    cudaGetSymbolAddress((void**)&bw_o, g_bw_o);
    cudaGetSymbolAddress((void**)&bw_e, g_bw_e);
    cudaGetSymbolAddress((void**)&bw_k, g_bw_k);
    cudaGetSymbolAddress((void**)&a_e_src, g_a_e_src);
    cudaGetSymbolAddress((void**)&a_o_dst_e2o, g_a_o_dst_e2o);
    cudaGetSymbolAddress((void**)&a_o_src_o2o, g_a_o_src_o2o);
    cudaGetSymbolAddress((void**)&a_o_dst_o2o, g_a_o_dst_o2o);
    cudaGetSymbolAddress((void**)&kdot, g_kdot);
    cudaGetSymbolAddress((void**)&outsum, g_outsum);
    cudaGetSymbolAddress((void**)&deg0, g_deg0);
    cudaGetSymbolAddress((void**)&deg1, g_deg1);
    cudaGetSymbolAddress((void**)&slots0, g_slots0);
    cudaGetSymbolAddress((void**)&slots1, g_slots1);

    dim3 gemmGrid(DK / 128, (N_NODE + 127) / 128);
    int cwBlocks = (DK * DK / 2 + 255) / 256;

    init_kernel<<<(N_NODE + 255) / 256, 256>>>();
    convert_w<<<cwBlocks, 256>>>(proj_o_w, bw_o);
    convert_w<<<cwBlocks, 256>>>(proj_e_w, bw_e);
    convert_w<<<cwBlocks, 256>>>(k_lin_w, bw_k);

    // projection GEMMs with fused attention-scalar epilogues
    mma_gemm<0,0,3><<<gemmGrid, 256>>>(
        x_o, bw_o, proj_o_b, h_o,
        att_dst_e2o, att_src_o2o, att_dst_o2o,
        a_o_dst_e2o, a_o_src_o2o, a_o_dst_o2o,
        nullptr, nullptr, N_NODE);
    mma_gemm<0,0,1><<<gemmGrid, 256>>>(
        x_e, bw_e, proj_e_b, h_e,
        att_src_e2o, nullptr, nullptr,
        a_e_src, nullptr, nullptr,
        nullptr, nullptr, N_NODE);

    build_csr<<<(NE + 255) / 256, 256>>>(e_e2o + NE, deg0, slots0);
    build_csr<<<(NE + 255) / 256, 256>>>(e_o2o + NE, deg1, slots1);

    conv_kernel<<<(N_NODE + 7) / 8, 256>>>(h_e, a_e_src, a_o_dst_e2o,
                                           e_e2o, deg0, slots0, out0, outsum);
    conv_kernel<<<(N_NODE + 7) / 8, 256>>>(h_o, a_o_src_o2o, a_o_dst_o2o,
                                           e_o2o, deg1, slots1, out1, outsum + DK);

    // semantic k GEMMs (tanh + q-dot scalar reduce)
    mma_gemm<1,1,0><<<gemmGrid, 256>>>(
        out0, bw_k, k_lin_b, nullptr,
        nullptr, nullptr, nullptr, nullptr, nullptr, nullptr,
        q_sem, kdot, N_NODE);
    mma_gemm<1,1,0><<<gemmGrid, 256>>>(
        out1, bw_k, k_lin_b, nullptr,
        nullptr, nullptr, nullptr, nullptr, nullptr, nullptr,
        q_sem, kdot + 1, N_NODE);

    finalize_kernel<<<1, 512>>>(lin_w, lin_b, out);
}

// round 8
// speedup vs baseline: 5.0822x; 1.0849x over previous
#include <cuda_runtime.h>
#include <cuda_bf16.h>
#include <math.h>

#define N_NODE 100000
#define NE     150000
#define DK     512
#define NH     8
#define CAP    64

// ---------------- scratch (device globals, allocation-free) ----------------
__device__ __nv_bfloat16 g_h_o[(size_t)N_NODE * DK];
__device__ __nv_bfloat16 g_h_e[(size_t)N_NODE * DK];
__device__ __nv_bfloat16 g_out0[(size_t)N_NODE * DK];
__device__ __nv_bfloat16 g_out1[(size_t)N_NODE * DK];
__device__ __nv_bfloat16 g_x_o_bf[(size_t)N_NODE * DK];
__device__ __nv_bfloat16 g_x_e_bf[(size_t)N_NODE * DK];

__device__ __nv_bfloat16 g_bw_o[DK * DK];   // bf16 weights, [k, n] layout
__device__ __nv_bfloat16 g_bw_e[DK * DK];
__device__ __nv_bfloat16 g_bw_k[DK * DK];

__device__ float g_a_e_src[(size_t)N_NODE * NH];
__device__ float g_a_o_dst_e2o[(size_t)N_NODE * NH];
__device__ float g_a_o_src_o2o[(size_t)N_NODE * NH];
__device__ float g_a_o_dst_o2o[(size_t)N_NODE * NH];

__device__ int g_deg0[N_NODE];
__device__ int g_deg1[N_NODE];
__device__ int g_slots0[(size_t)N_NODE * CAP];
__device__ int g_slots1[(size_t)N_NODE * CAP];

__device__ float g_kdot[2];
__device__ float g_outsum[2 * DK];

__device__ __forceinline__ unsigned pack_bf16(float x, float y) {
    __nv_bfloat162 h = __floats2bfloat162_rn(x, y);
    return *reinterpret_cast<unsigned*>(&h);
}
__device__ __forceinline__ float2 unpack_bf16(unsigned u) {
    __nv_bfloat162 h = *reinterpret_cast<__nv_bfloat162*>(&u);
    return __bfloat1622float2(h);
}

// ---------------- init ----------------
__global__ void init_kernel() {
    int i = blockIdx.x * blockDim.x + threadIdx.x;
    if (i < N_NODE) { g_deg0[i] = 0; g_deg1[i] = 0; }
    if (i < 2 * DK) g_outsum[i] = 0.f;
    if (i < 2) g_kdot[i] = 0.f;
}

// ---------------- fp32 -> bf16 stream convert (float4 granularity) ----------------
__global__ void convert_f2b(const float* __restrict__ X, __nv_bfloat16* __restrict__ O, int n4) {
    int i = blockIdx.x * blockDim.x + threadIdx.x;
    if (i < n4) {
        float4 f = reinterpret_cast<const float4*>(X)[i];
        uint2 o;
        o.x = pack_bf16(f.x, f.y);
        o.y = pack_bf16(f.z, f.w);
        reinterpret_cast<uint2*>(O)[i] = o;
    }
}

// =====================================================================
// bf16 mma.sync GEMM with 3-stage cp.async pipeline.
// C[M,512] = A[M,512] @ B[512,512]  (A, B both bf16)
// EPI 0: bias + store bf16 C + NATT fused per-head attention dots
// EPI 1: sum_n sum_f tanh(c+bias)*q[f] -> one atomicAdd(kdot[z]) per block
//        (blockIdx.z selects A0/A1 and kdot slot)
// block 256 threads, tile 128x128, K-chunk 64, grid (4, ceil(M/128), 1 or 2)
// dyn smem: 3 stages x (A 16KB + B 16KB) = 96KB, + bias 2KB + aux 6KB
// =====================================================================
#define SM_STAGES 98304
#define SM_BIAS   98304
#define SM_AUX    (98304 + 2048)
#define SM_TOTAL  (98304 + 2048 + 6144)

template<int EPI, int NATT>
__global__ __launch_bounds__(256)
void mma_gemm(const __nv_bfloat16* __restrict__ A0, const __nv_bfloat16* __restrict__ A1,
              const __nv_bfloat16* __restrict__ B,
              const float* __restrict__ bias, __nv_bfloat16* __restrict__ Cout,
              const float* __restrict__ av0, const float* __restrict__ av1,
              const float* __restrict__ av2,
              float* __restrict__ aout0, float* __restrict__ aout1,
              float* __restrict__ aout2,
              const float* __restrict__ qsem, float* __restrict__ kdot, int M) {
    extern __shared__ __align__(16) unsigned char dsm[];
    __shared__ float wred[8];
    unsigned sbase = (unsigned)__cvta_generic_to_shared(dsm);
    float* bias_sh = (float*)(dsm + SM_BIAS);
    float* aux_sh  = (float*)(dsm + SM_AUX);

    int tid = threadIdx.x;
    int lane = tid & 31, wid = tid >> 5;
    int warp_m = wid & 3, warp_n = wid >> 2;      // 4 x 2 warps; warp tile 32x64
    int rowBase = blockIdx.y * 128;
    int colBase = blockIdx.x * 128;

    const __nv_bfloat16* A = (EPI == 1 && blockIdx.z == 1) ? A1 : A0;

    for (int i = tid; i < DK; i += 256) {
        bias_sh[i] = bias[i];
        if (EPI == 1) aux_sh[i] = qsem[i];
    }
    if (EPI == 0 && NATT > 0) {
        for (int i = tid; i < NATT * DK; i += 256) {
            const float* src = (i < DK) ? av0 : (i < 2 * DK) ? av1 : av2;
            aux_sh[i] = src[i & (DK - 1)];
        }
    }

    float c[2][8][4];
#pragma unroll
    for (int i = 0; i < 2; i++)
#pragma unroll
        for (int j = 0; j < 8; j++)
#pragma unroll
            for (int q = 0; q < 4; q++) c[i][j][q] = 0.f;

    auto issue = [&](int ch) {
        int st = ch % 3;
        unsigned abase = sbase + st * 32768;
        int k0 = ch * 64;
#pragma unroll
        for (int i = 0; i < 4; i++) {
            int idx = tid + 256 * i;
            {   // A tile: 128 rows x 128B
                int r = idx >> 3, c16 = idx & 7;
                int gr = rowBase + r;
                int sz = (gr < M) ? 16 : 0;
                int ga = gr < M ? gr : (M - 1);
                const __nv_bfloat16* src = A + (size_t)ga * DK + k0 + c16 * 8;
                unsigned dst = abase + (r * 8 + (c16 ^ (r & 7))) * 16;
                asm volatile("cp.async.cg.shared.global [%0], [%1], 16, %2;"
                             :: "r"(dst), "l"(src), "r"(sz));
            }
            {   // B tile: 64 rows x 256B
                int r = idx >> 4, cch = idx & 15;
                const __nv_bfloat16* src = B + (size_t)(k0 + r) * DK + colBase + cch * 8;
                unsigned dst = abase + 16384 + (r * 16 + ((cch & 8) | ((cch & 7) ^ (r & 7)))) * 16;
                asm volatile("cp.async.cg.shared.global [%0], [%1], 16;"
                             :: "r"(dst), "l"(src));
            }
        }
    };

    issue(0); asm volatile("cp.async.commit_group;" ::: "memory");
    issue(1); asm volatile("cp.async.commit_group;" ::: "memory");

    for (int ch = 0; ch < 8; ch++) {
        if (ch == 7) asm volatile("cp.async.wait_group 0;" ::: "memory");
        else         asm volatile("cp.async.wait_group 1;" ::: "memory");
        __syncthreads();
        if (ch + 2 < 8) {
            issue(ch + 2);
            asm volatile("cp.async.commit_group;" ::: "memory");
        }
        unsigned AsB = sbase + (ch % 3) * 32768;
        unsigned BsB = AsB + 16384;
#pragma unroll
        for (int kk = 0; kk < 4; kk++) {
            unsigned a[2][4], b[8][2];
#pragma unroll
            for (int i = 0; i < 2; i++) {
                int m = lane >> 3;
                int r = warp_m * 32 + i * 16 + (m & 1) * 8 + (lane & 7);
                int cch = kk * 2 + (m >> 1);
                unsigned addr = AsB + r * 128 + ((cch ^ (r & 7)) * 16);
                asm volatile("ldmatrix.sync.aligned.m8n8.x4.shared.b16 {%0,%1,%2,%3}, [%4];"
                             : "=r"(a[i][0]), "=r"(a[i][1]), "=r"(a[i][2]), "=r"(a[i][3]) : "r"(addr));
            }
#pragma unroll
            for (int jp = 0; jp < 4; jp++) {
                int m = lane >> 3;
                int kr = kk * 16 + (m & 1) * 8 + (lane & 7);
                int cch = warp_n * 8 + jp * 2 + (m >> 1);
                unsigned addr = BsB + kr * 256 + (((cch & 8) | ((cch & 7) ^ (kr & 7))) * 16);
                asm volatile("ldmatrix.sync.aligned.m8n8.x4.trans.shared.b16 {%0,%1,%2,%3}, [%4];"
                             : "=r"(b[jp*2][0]), "=r"(b[jp*2][1]), "=r"(b[jp*2+1][0]), "=r"(b[jp*2+1][1])
                             : "r"(addr));
            }
#pragma unroll
            for (int i = 0; i < 2; i++)
#pragma unroll
                for (int j = 0; j < 8; j++) {
                    asm volatile(
                        "mma.sync.aligned.m16n8k16.row.col.f32.bf16.bf16.f32 "
                        "{%0,%1,%2,%3}, {%4,%5,%6,%7}, {%8,%9}, {%0,%1,%2,%3};"
                        : "+f"(c[i][j][0]), "+f"(c[i][j][1]), "+f"(c[i][j][2]), "+f"(c[i][j][3])
                        : "r"(a[i][0]), "r"(a[i][1]), "r"(a[i][2]), "r"(a[i][3]),
                          "r"(b[j][0]), "r"(b[j][1]));
                }
        }
    }

    // ---------------- epilogue ----------------
    int g = lane >> 2, t = lane & 3;
    if (EPI == 0) {
        __nv_bfloat16* C = Cout;
        float aacc[(NATT > 0 ? NATT : 1)][4];
#pragma unroll
        for (int v = 0; v < (NATT > 0 ? NATT : 1); v++)
#pragma unroll
            for (int f = 0; f < 4; f++) aacc[v][f] = 0.f;

#pragma unroll
        for (int j = 0; j < 8; j++) {
            int col = colBase + warp_n * 64 + j * 8 + 2 * t;
            float b0 = bias_sh[col], b1 = bias_sh[col + 1];
#pragma unroll
            for (int i = 0; i < 2; i++) {
                int r0 = rowBase + warp_m * 32 + i * 16 + g;
                float v0 = c[i][j][0] + b0, v1 = c[i][j][1] + b1;
                float v2 = c[i][j][2] + b0, v3 = c[i][j][3] + b1;
                if (r0 < M)
                    *reinterpret_cast<unsigned*>(C + (size_t)r0 * DK + col) = pack_bf16(v0, v1);
                if (r0 + 8 < M)
                    *reinterpret_cast<unsigned*>(C + (size_t)(r0 + 8) * DK + col) = pack_bf16(v2, v3);
#pragma unroll
                for (int v = 0; v < NATT; v++) {
                    float a0 = aux_sh[v * DK + col], a1 = aux_sh[v * DK + col + 1];
                    aacc[v][i * 2 + 0] += v0 * a0 + v1 * a1;
                    aacc[v][i * 2 + 1] += v2 * a0 + v3 * a1;
                }
            }
        }
        if (NATT > 0) {
            // reduce over the 4 't' lanes (each (bx, warp_n) owns one head's 64 cols)
#pragma unroll
            for (int v = 0; v < NATT; v++)
#pragma unroll
                for (int f = 0; f < 4; f++) {
                    aacc[v][f] += __shfl_xor_sync(0xffffffffu, aacc[v][f], 1);
                    aacc[v][f] += __shfl_xor_sync(0xffffffffu, aacc[v][f], 2);
                }
            if (t == 0) {
                int ghead = blockIdx.x * 2 + warp_n;
#pragma unroll
                for (int f = 0; f < 4; f++) {
                    int row = rowBase + warp_m * 32 + (f & 1) * 8 + (f >> 1) * 16 + g;
                    if (row < M) {
#pragma unroll
                        for (int v = 0; v < NATT; v++) {
                            float* ao = (v == 0) ? aout0 : (v == 1) ? aout1 : aout2;
                            ao[(size_t)row * NH + ghead] = aacc[v][f];
                        }
                    }
                }
            }
        }
    } else {
        float sq = 0.f;
#pragma unroll
        for (int j = 0; j < 8; j++) {
            int col = colBase + warp_n * 64 + j * 8 + 2 * t;
            float b0 = bias_sh[col], b1 = bias_sh[col + 1];
            float q0 = aux_sh[col], q1 = aux_sh[col + 1];
#pragma unroll
            for (int i = 0; i < 2; i++) {
                int r0 = rowBase + warp_m * 32 + i * 16 + g;
                if (r0 < M)
                    sq += tanhf(c[i][j][0] + b0) * q0 + tanhf(c[i][j][1] + b1) * q1;
                if (r0 + 8 < M)
                    sq += tanhf(c[i][j][2] + b0) * q0 + tanhf(c[i][j][3] + b1) * q1;
            }
        }
#pragma unroll
        for (int off = 16; off > 0; off >>= 1)
            sq += __shfl_xor_sync(0xffffffffu, sq, off);
        if (lane == 0) wred[wid] = sq;
        __syncthreads();
        if (tid == 0) {
            float s = 0.f;
#pragma unroll
            for (int w = 0; w < 8; w++) s += wred[w];
            atomicAdd(&kdot[blockIdx.z], s);
        }
    }
}

// ---------------- padded-CSR build ----------------
__global__ void build_csr(const int* __restrict__ dst, int* __restrict__ deg,
                          int* __restrict__ slots) {
    int e = blockIdx.x * blockDim.x + threadIdx.x;
    if (e >= NE) return;
    int dn = dst[e];
    int pos = atomicAdd(&deg[dn], 1);
    if (pos < CAP) slots[(size_t)dn * CAP + pos] = e;
}

// ---------------- GAT conv: one warp per dst node, 2-pass with smem-cached
// logits + online softmax; bf16 feature gather; fused colsum ----------------
__global__ void conv_kernel(const __nv_bfloat16* __restrict__ hsrc,
                            const float* __restrict__ asrc,
                            const float* __restrict__ adst,
                            const int* __restrict__ esrc,
                            const int* __restrict__ deg,
                            const int* __restrict__ slots,
                            __nv_bfloat16* __restrict__ outp,
                            float* __restrict__ outsum) {
    __shared__ float al_sm[8][CAP][NH];   // 16KB
    __shared__ int   sidx[8][CAP];        // 2KB
    __shared__ float mx_sm[8][NH];
    __shared__ float den_sm[8][NH];
    __shared__ float bsum[512];
    for (int i = threadIdx.x; i < 512; i += 256) bsum[i] = 0.f;
    __syncthreads();

    int warp = threadIdx.x >> 5, lane = threadIdx.x & 31;
    int n = blockIdx.x * 8 + warp;
    float acc[16];
#pragma unroll
    for (int r = 0; r < 16; r++) acc[r] = 0.f;

    if (n < N_NODE) {
        int d = deg[n]; if (d > CAP) d = CAP;
        if (d > 0) {
            int h = lane & 7, q = lane >> 3;   // 4 edges x 8 heads per pass step
            float ad = adst[(size_t)n * NH + h];
            const int* sl = slots + (size_t)n * CAP;

            // ---- pass 1: logits -> smem, online softmax per lane ----
            float mx = -1e30f, den = 0.f;
            for (int j0 = 0; j0 < d; j0 += 4) {
                int jj = j0 + q;
                if (jj < d) {
                    int s = esrc[sl[jj]];
                    if (h == 0) sidx[warp][jj] = s;
                    float al = asrc[(size_t)s * NH + h] + ad;
                    al = al > 0.f ? al : 0.2f * al;
                    al_sm[warp][jj][h] = al;
                    float nm = fmaxf(mx, al);
                    den = den * __expf(mx - nm) + __expf(al - nm);
                    mx = nm;
                }
            }
            // combine lanes {h, h+8, h+16, h+24}
#pragma unroll
            for (int off = 8; off <= 16; off <<= 1) {
                float mo = __shfl_xor_sync(0xffffffffu, mx, off);
                float dn_ = __shfl_xor_sync(0xffffffffu, den, off);
                float nm = fmaxf(mx, mo);
                den = den * __expf(mx - nm) + dn_ * __expf(mo - nm);
                mx = nm;
            }
            if (q == 0) { mx_sm[warp][h] = mx; den_sm[warp][h] = den + 1e-16f; }
            __syncwarp();

            // ---- pass 2: weighted feature gather ----
            int h1 = lane >> 3, h2 = 4 + h1;
            float m1 = mx_sm[warp][h1], d1 = den_sm[warp][h1];
            float m2 = mx_sm[warp][h2], d2 = den_sm[warp][h2];
            for (int j = 0; j < d; j++) {
                int s = sidx[warp][j];
                float w1 = __expf(al_sm[warp][j][h1] - m1) / d1;
                float w2 = __expf(al_sm[warp][j][h2] - m2) / d2;
                const uint4* hp = reinterpret_cast<const uint4*>(hsrc + (size_t)s * DK);
                uint4 v1 = hp[lane];
                uint4 v2 = hp[lane + 32];
                const unsigned* u1 = &v1.x;
                const unsigned* u2 = &v2.x;
#pragma unroll
                for (int qq = 0; qq < 4; qq++) {
                    float2 f1 = unpack_bf16(u1[qq]);
                    float2 f2 = unpack_bf16(u2[qq]);
                    acc[qq * 2 + 0] += f1.x * w1; acc[qq * 2 + 1] += f1.y * w1;
                    acc[8 + qq * 2 + 0] += f2.x * w2; acc[8 + qq * 2 + 1] += f2.y * w2;
                }
            }
        }
        uint4 o1, o2;
        unsigned* p1 = &o1.x; unsigned* p2 = &o2.x;
#pragma unroll
        for (int qq = 0; qq < 4; qq++) {
            float a0 = fmaxf(acc[qq*2+0], 0.f),  a1 = fmaxf(acc[qq*2+1], 0.f);
            float b0 = fmaxf(acc[8+qq*2+0], 0.f), b1 = fmaxf(acc[8+qq*2+1], 0.f);
            p1[qq] = pack_bf16(a0, a1);
            p2[qq] = pack_bf16(b0, b1);
            atomicAdd(&bsum[lane * 8 + qq * 2 + 0], a0);
            atomicAdd(&bsum[lane * 8 + qq * 2 + 1], a1);
            atomicAdd(&bsum[256 + lane * 8 + qq * 2 + 0], b0);
            atomicAdd(&bsum[256 + lane * 8 + qq * 2 + 1], b1);
        }
        uint4* op = reinterpret_cast<uint4*>(outp + (size_t)n * DK);
        op[lane] = o1; op[lane + 32] = o2;
    }
    __syncthreads();
    for (int i = threadIdx.x; i < 512; i += 256) atomicAdd(&outsum[i], bsum[i]);
}

// ---------------- finalize ----------------
__global__ void finalize_kernel(const float* __restrict__ lw,
                                const float* __restrict__ lb,
                                float* __restrict__ out) {
    __shared__ float red0[512], red1[512];
    __shared__ float sem0s, sem1s;
    int t = threadIdx.x;
    if (t == 0) {
        float s0 = g_kdot[0] / (float)N_NODE;
        float s1 = g_kdot[1] / (float)N_NODE;
        float mx = fmaxf(s0, s1);
        float e0 = expf(s0 - mx), e1 = expf(s1 - mx);
        sem0s = e0 / (e0 + e1);
        sem1s = e1 / (e0 + e1);
    }
    __syncthreads();
    float pooled = (sem0s * g_outsum[t] + sem1s * g_outsum[DK + t]) / (float)N_NODE;
    red0[t] = pooled * lw[t * 2 + 0];
    red1[t] = pooled * lw[t * 2 + 1];
    __syncthreads();
    for (int s = 256; s > 0; s >>= 1) {
        if (t < s) { red0[t] += red0[t + s]; red1[t] += red1[t + s]; }
        __syncthreads();
    }
    if (t == 0) {
        out[0] = red0[0] + lb[0];
        out[1] = red1[0] + lb[1];
    }
}

// ---------------- launch ----------------
extern "C" void kernel_launch(void* const* d_in, const int* in_sizes, int n_in,
                              void* d_out, int out_size) {
    const float* x_o        = (const float*)d_in[0];
    const float* x_e        = (const float*)d_in[1];
    const int*   e_e2o      = (const int*)d_in[2];
    const int*   e_o2o      = (const int*)d_in[3];
    const float* proj_o_w   = (const float*)d_in[4];
    const float* proj_o_b   = (const float*)d_in[5];
    const float* proj_e_w   = (const float*)d_in[6];
    const float* proj_e_b   = (const float*)d_in[7];
    const float* att_src_e2o= (const float*)d_in[8];
    const float* att_dst_e2o= (const float*)d_in[9];
    const float* att_src_o2o= (const float*)d_in[10];
    const float* att_dst_o2o= (const float*)d_in[11];
    const float* k_lin_w    = (const float*)d_in[12];
    const float* k_lin_b    = (const float*)d_in[13];
    const float* q_sem      = (const float*)d_in[14];
    const float* lin_w      = (const float*)d_in[15];
    const float* lin_b      = (const float*)d_in[16];
    float* out = (float*)d_out;

    __nv_bfloat16 *h_o, *h_e, *out0, *out1, *bw_o, *bw_e, *bw_k, *x_o_bf, *x_e_bf;
    float *a_e_src, *a_o_dst_e2o, *a_o_src_o2o, *a_o_dst_o2o, *kdot, *outsum;
    int *deg0, *deg1, *slots0, *slots1;
    cudaGetSymbolAddress((void**)&h_o, g_h_o);
    cudaGetSymbolAddress((void**)&h_e, g_h_e);
    cudaGetSymbolAddress((void**)&out0, g_out0);
    cudaGetSymbolAddress((void**)&out1, g_out1);
    cudaGetSymbolAddress((void**)&bw_o, g_bw_o);
    cudaGetSymbolAddress((void**)&bw_e, g_bw_e);
    cudaGetSymbolAddress((void**)&bw_k, g_bw_k);
    cudaGetSymbolAddress((void**)&x_o_bf, g_x_o_bf);
    cudaGetSymbolAddress((void**)&x_e_bf, g_x_e_bf);
    cudaGetSymbolAddress((void**)&a_e_src, g_a_e_src);
    cudaGetSymbolAddress((void**)&a_o_dst_e2o, g_a_o_dst_e2o);
    cudaGetSymbolAddress((void**)&a_o_src_o2o, g_a_o_src_o2o);
    cudaGetSymbolAddress((void**)&a_o_dst_o2o, g_a_o_dst_o2o);
    cudaGetSymbolAddress((void**)&kdot, g_kdot);
    cudaGetSymbolAddress((void**)&outsum, g_outsum);
    cudaGetSymbolAddress((void**)&deg0, g_deg0);
    cudaGetSymbolAddress((void**)&deg1, g_deg1);
    cudaGetSymbolAddress((void**)&slots0, g_slots0);
    cudaGetSymbolAddress((void**)&slots1, g_slots1);

    cudaFuncSetAttribute(mma_gemm<0,3>, cudaFuncAttributeMaxDynamicSharedMemorySize, SM_TOTAL);
    cudaFuncSetAttribute(mma_gemm<0,1>, cudaFuncAttributeMaxDynamicSharedMemorySize, SM_TOTAL);
    cudaFuncSetAttribute(mma_gemm<1,0>, cudaFuncAttributeMaxDynamicSharedMemorySize, SM_TOTAL);

    dim3 projGrid(DK / 128, (N_NODE + 127) / 128, 1);
    dim3 kGrid(DK / 128, (N_NODE + 127) / 128, 2);
    int xN4 = N_NODE * DK / 4;     // 12.8M float4s
    int wN4 = DK * DK / 4;

    init_kernel<<<(N_NODE + 255) / 256, 256>>>();
    convert_f2b<<<(wN4 + 255) / 256, 256>>>(proj_o_w, bw_o, wN4);
    convert_f2b<<<(wN4 + 255) / 256, 256>>>(proj_e_w, bw_e, wN4);
    convert_f2b<<<(wN4 + 255) / 256, 256>>>(k_lin_w, bw_k, wN4);
    convert_f2b<<<(xN4 + 255) / 256, 256>>>(x_o, x_o_bf, xN4);
    convert_f2b<<<(xN4 + 255) / 256, 256>>>(x_e, x_e_bf, xN4);

    // projection GEMMs with fused attention-scalar epilogues
    mma_gemm<0,3><<<projGrid, 256, SM_TOTAL>>>(
        x_o_bf, nullptr, bw_o, proj_o_b, h_o,
        att_dst_e2o, att_src_o2o, att_dst_o2o,
        a_o_dst_e2o, a_o_src_o2o, a_o_dst_o2o,
        nullptr, nullptr, N_NODE);
    mma_gemm<0,1><<<projGrid, 256, SM_TOTAL>>>(
        x_e_bf, nullptr, bw_e, proj_e_b, h_e,
        att_src_e2o, nullptr, nullptr,
        a_e_src, nullptr, nullptr,
        nullptr, nullptr, N_NODE);

    build_csr<<<(NE + 255) / 256, 256>>>(e_e2o + NE, deg0, slots0);
    build_csr<<<(NE + 255) / 256, 256>>>(e_o2o + NE, deg1, slots1);

    conv_kernel<<<(N_NODE + 7) / 8, 256>>>(h_e, a_e_src, a_o_dst_e2o,
                                           e_e2o, deg0, slots0, out0, outsum);
    conv_kernel<<<(N_NODE + 7) / 8, 256>>>(h_o, a_o_src_o2o, a_o_dst_o2o,
                                           e_o2o, deg1, slots1, out1, outsum + DK);

    // both semantic k GEMMs in one launch (z selects metapath)
    mma_gemm<1,0><<<kGrid, 256, SM_TOTAL>>>(
        out0, out1, bw_k, k_lin_b, nullptr,
        nullptr, nullptr, nullptr, nullptr, nullptr, nullptr,
        q_sem, kdot, N_NODE);

    finalize_kernel<<<1, 512>>>(lin_w, lin_b, out);
}